// round 9
// baseline (speedup 1.0000x reference)
#include <cuda_runtime.h>
#include <math.h>
#include <stdint.h>
#include <float.h>

#define LNUM 2
#define HID 512
#define TMAX 20
#define VOC 10000
#define BAT 32
#define SPA 49
#define G4 2048
#define KXH 1024
#define VLD 10240
#define NB 296
#define NT 256
#define NGRP 37     // 296 / 8

typedef unsigned long long u64;

__device__ __forceinline__ u64 ffma2(u64 a, u64 b, u64 c) {
    u64 d; asm("fma.rn.f32x2 %0, %1, %2, %3;" : "=l"(d) : "l"(a), "l"(b), "l"(c)); return d;
}
__device__ __forceinline__ u64 fadd2(u64 a, u64 b) {
    u64 d; asm("add.rn.f32x2 %0, %1, %2;" : "=l"(d) : "l"(a), "l"(b)); return d;
}
__device__ __forceinline__ u64 dup2(float x) {
    u64 d; unsigned u = __float_as_uint(x);
    asm("mov.b64 %0, {%1, %2};" : "=l"(d) : "r"(u), "r"(u)); return d;
}
__device__ __forceinline__ u64 pack2(float x, float y) {
    u64 d; unsigned a = __float_as_uint(x), b = __float_as_uint(y);
    asm("mov.b64 %0, {%1, %2};" : "=l"(d) : "r"(a), "r"(b)); return d;
}
__device__ __forceinline__ float lo2(u64 v) { return __uint_as_float((unsigned)v); }
__device__ __forceinline__ float hi2(u64 v) { return __uint_as_float((unsigned)(v >> 32)); }
__device__ __forceinline__ float sigm(float x) { return 1.f / (1.f + expf(-x)); }

// ---------------- static device scratch ----------------
__device__ float d_WcT[LNUM][KXH][G4];        // [l][k][n]
__device__ float d_WqT[HID][HID];             // [k][d]
__device__ float d_hattWT[KXH][HID];          // [k][j]
__device__ float d_projWT[HID][VLD];          // [k][v] padded (pad stays 0)
__device__ float d_keys[BAT][SPA][HID];
__device__ float d_vals[BAT][SPA][HID];
__device__ float d_hA[LNUM][BAT][HID];
__device__ float d_hB[LNUM][BAT][HID];
__device__ float d_cst[LNUM][BAT][HID];
__device__ float d_q[LNUM*BAT][HID];
__device__ float d_attn[LNUM*BAT][HID];
__device__ float d_P1[32][BAT][G4];           // LSTM partials (ksplit 32)
__device__ float d_P2[16][BAT][VLD];          // proj partials (ksplit 13)
__device__ float d_Pq[16][LNUM*BAT][HID];     // q partials (ksplit 16)
__device__ float d_Ph[32][LNUM*BAT][HID];     // hatt partials (ksplit 32)
__device__ float d_logits[TMAX][BAT][VOC];
__device__ u64   d_bestKey[BAT];
__device__ int   d_best[BAT];
// tree barrier state: monotonic, never reset (safe across graph replays)
__device__ unsigned g_grp[NGRP * 32];         // one counter per 128B
__device__ unsigned g_root;
__device__ volatile unsigned g_genv;

// ---------------- multi-job transposes ----------------
__global__ void transA(const float* __restrict__ Wih, const float* __restrict__ Whh) {
    __shared__ float tile[32][33];
    int z = blockIdx.z;
    const float* in = (z & 1) ? Whh : Wih;
    if (z >= 2) in += 2048 * 512;
    float* out = &d_WcT[0][0][0] + (size_t)(z >= 2 ? KXH : 0) * G4 + (size_t)(z & 1 ? 512 : 0) * G4;
    int c0 = blockIdx.x * 32, r0 = blockIdx.y * 32;
    int x = threadIdx.x;
    for (int y = threadIdx.y; y < 32; y += 8) {
        int r = r0 + y, c = c0 + x;
        tile[y][x] = (r < 2048 && c < 512) ? in[(size_t)r * 512 + c] : 0.f;
    }
    __syncthreads();
    for (int y = threadIdx.y; y < 32; y += 8) {
        int c = c0 + y, r = r0 + x;
        if (c < 512 && r < 2048) out[(size_t)c * G4 + r] = tile[x][y];
    }
}

__global__ void transB(const float* __restrict__ Wq, const float* __restrict__ hattW,
                       const float* __restrict__ projW) {
    __shared__ float tile[32][33];
    int z = blockIdx.z;
    const float* in; float* out; int R, C, oLd;
    if (z == 0)      { in = Wq;    out = &d_WqT[0][0];    R = 512;  C = 512;  oLd = 512; }
    else if (z == 1) { in = hattW; out = &d_hattWT[0][0]; R = 512;  C = 1024; oLd = 512; }
    else             { in = projW; out = &d_projWT[0][0]; R = VOC;  C = 512;  oLd = VLD; }
    int c0 = blockIdx.x * 32, r0 = blockIdx.y * 32;
    if (c0 >= C || r0 >= R) return;
    int x = threadIdx.x;
    for (int y = threadIdx.y; y < 32; y += 8) {
        int r = r0 + y, c = c0 + x;
        tile[y][x] = (r < R && c < C) ? in[(size_t)r * C + c] : 0.f;
    }
    __syncthreads();
    for (int y = threadIdx.y; y < 32; y += 8) {
        int c = c0 + y, r = r0 + x;
        if (c < C && r < R) out[(size_t)c * oLd + r] = tile[x][y];
    }
}

// ---------------- keys / values precompute + state init ----------------
__global__ void kvinit_kernel(const float* __restrict__ chan, const float* __restrict__ Wk,
                              const float* __restrict__ bk, const float* __restrict__ Wv,
                              const float* __restrict__ bv, const float* __restrict__ pooled,
                              const int* __restrict__ sosp) {
    int b = blockIdx.x;
    int d0 = blockIdx.y * 64;
    __shared__ float ct[64][SPA];
    __shared__ float wk[SPA][SPA], wv[SPA][SPA];
    __shared__ float bks[SPA], bvs[SPA];
    int tid = threadIdx.x;
    if (blockIdx.y == 0) {
        for (int j = tid; j < HID; j += 256) {
            float pv = pooled[b * HID + j];
            d_hA[0][b][j] = pv; d_hA[1][b][j] = pv;
            d_cst[0][b][j] = pv; d_cst[1][b][j] = pv;
        }
        if (tid == 0) d_best[b] = sosp[0];
        // NOTE: barrier counters are monotonic; never reset here.
    }
    for (int i = tid; i < 64 * SPA; i += 256) {
        int d = i / SPA, s = i % SPA;
        ct[d][s] = chan[((size_t)b * HID + d0 + d) * SPA + s];
    }
    for (int i = tid; i < SPA * SPA; i += 256) {
        wk[i / SPA][i % SPA] = Wk[i];
        wv[i / SPA][i % SPA] = Wv[i];
    }
    if (tid < SPA) { bks[tid] = bk[tid]; bvs[tid] = bv[tid]; }
    __syncthreads();
    for (int i = tid; i < SPA * 64; i += 256) {
        int d = i & 63, s = i >> 6;
        float ak = bks[s], av = bvs[s];
#pragma unroll
        for (int sp = 0; sp < SPA; sp++) {
            float cv = ct[d][sp];
            ak += cv * wk[s][sp];
            av += cv * wv[s][sp];
        }
        d_keys[b][s][d0 + d] = tanhf(ak);
        d_vals[b][s][d0 + d] = tanhf(av);
    }
}

// ---------------- res[:,:,0] (identical across batch) ----------------
__global__ void logits0_kernel(const float* __restrict__ embed, const int* __restrict__ sosp,
                               const float* __restrict__ projW, const float* __restrict__ projb) {
    int warp = threadIdx.x >> 5, lane = threadIdx.x & 31;
    int v = blockIdx.x * 8 + warp;
    if (v >= VOC) return;
    int sos = sosp[0];
    const float* e = embed + (size_t)sos * HID;
    const float* w = projW + (size_t)v * HID;
    float acc = 0.f;
    for (int k = lane; k < HID; k += 32) acc += e[k] * w[k];
    for (int o = 16; o; o >>= 1) acc += __shfl_xor_sync(0xffffffffu, acc, o);
    float s = acc + projb[v];
    d_logits[0][lane][v] = s;   // lane == b
}

// ---------------- tree grid barrier ----------------
__device__ __forceinline__ void gsync(unsigned& gen, int bid) {
    __syncthreads();
    if (threadIdx.x == 0) {
        gen++;
        __threadfence();
        unsigned a = atomicAdd(&g_grp[(bid >> 3) * 32], 1u) + 1u;
        if (a == gen * 8u) {
            unsigned r = atomicAdd(&g_root, 1u) + 1u;
            if (r == gen * (unsigned)NGRP) {
                __threadfence();
                g_genv = gen;
            }
        }
        while (g_genv < gen) {}
        __threadfence();
    }
    __syncthreads();
}

__global__ void __launch_bounds__(NT, 2) decode_loop(
    const float* __restrict__ embed, const float* __restrict__ bih,
    const float* __restrict__ bhh, const float* __restrict__ projb,
    const float* __restrict__ bq, const float* __restrict__ hattb)
{
    unsigned gen = g_genv;                      // monotonic, replay-safe
    int bid = blockIdx.x, tid = threadIdx.x;
    __shared__ __align__(16) char shraw[64 * 33 * 8];    // 16.9KB union
    __shared__ int sbest[32];
    u64   (*As2)[33] = (u64(*)[33])shraw;
    float* xs  = (float*)shraw;
    float* wts = (float*)(shraw + 2048);
    float* red = (float*)shraw;
    int*   ridx = (int*)(shraw + 1024);

    const float* hA0 = &d_hA[0][0][0];
    const float* hA1 = &d_hA[1][0][0];
    const float* hB0 = &d_hB[0][0][0];
    const float* hB1 = &d_hB[1][0][0];

    for (int t = 0; t < TMAX - 1; t++) {
        // ===== A / C: LSTM gemm f32x2 (32ks x 4nt = 128 blocks, KC=32) =====
        for (int l = 0; l < 2; l++) {
            if (bid < 128) {
                int ks = bid >> 2, nt = bid & 3, k0 = ks * 32;
                if (l == 0) {
                    if (tid < 32) sbest[tid] = d_best[tid];
                }
                __syncthreads();
                for (int i = tid; i < 1024; i += NT) {
                    int kk = i & 31, m = i >> 5, k = k0 + kk;
                    float v;
                    if (l == 0) v = (k < 512) ? embed[(size_t)sbest[m] * HID + k] : hA0[m * HID + (k - 512)];
                    else        v = (k < 512) ? hB0[m * HID + k] : hA1[m * HID + (k - 512)];
                    As2[kk][m] = dup2(v);
                }
                __syncthreads();
                int np = nt * 256 + tid;                 // 0..1023 n-pair
                const u64* Bp = (const u64*)&d_WcT[l][k0][0] + np;
                u64 acc[32];
#pragma unroll
                for (int m = 0; m < 32; m++) acc[m] = 0ull;
#pragma unroll 4
                for (int kk = 0; kk < 32; kk++) {
                    u64 bv = __ldg(Bp); Bp += G4 / 2;
#pragma unroll
                    for (int m = 0; m < 32; m++) acc[m] = ffma2(As2[kk][m], bv, acc[m]);
                }
                u64* Pp = (u64*)&d_P1[0][0][0] + (size_t)(ks * 32) * (G4 / 2) + np;
#pragma unroll
                for (int m = 0; m < 32; m++) Pp[(size_t)m * (G4 / 2)] = acc[m];
            }
            gsync(gen, bid);
            // ===== B / D: activation (64 blocks) =====
            if (bid < 64) {
                int out = bid * 256 + tid;
                int b = out >> 9, j = out & 511;
                float s0 = bih[l * G4 + j]        + bhh[l * G4 + j];
                float s1 = bih[l * G4 + 512 + j]  + bhh[l * G4 + 512 + j];
                float s2 = bih[l * G4 + 1024 + j] + bhh[l * G4 + 1024 + j];
                float s3 = bih[l * G4 + 1536 + j] + bhh[l * G4 + 1536 + j];
                const float* P = &d_P1[0][0][0];
#pragma unroll 8
                for (int ks = 0; ks < 32; ks++) {
                    size_t base = (size_t)(ks * 32 + b) * G4 + j;
                    s0 += P[base];
                    s1 += P[base + 512];
                    s2 += P[base + 1024];
                    s3 += P[base + 1536];
                }
                float i_ = sigm(s0), f_ = sigm(s1), gg = tanhf(s2), o_ = sigm(s3);
                float c2 = f_ * d_cst[l][b][j] + i_ * gg;
                float h2 = o_ * tanhf(c2);
                d_cst[l][b][j] = c2;
                d_hB[l][b][j] = h2;
            }
            gsync(gen, bid);
        }
        // ===== E: proj gemm (13ks x 20nt = 260) || q gemm (16ks x 2l = 32) =====
        if (bid < 260) {
            int nt = bid % 20, ks = bid / 20;
            int k0 = (ks * 512) / 13, k1 = ((ks + 1) * 512) / 13;
            int kc = k1 - k0;
            __syncthreads();
            for (int i = tid; i < 32 * kc; i += NT) {
                int kk = i % kc, m = i / kc;
                As2[kk][m] = dup2(hB1[m * HID + k0 + kk]);
            }
            __syncthreads();
            int np = nt * 256 + tid;
            const u64* Bp = (const u64*)&d_projWT[k0][0] + np;
            u64 acc[32];
#pragma unroll
            for (int m = 0; m < 32; m++) acc[m] = 0ull;
#pragma unroll 4
            for (int kk = 0; kk < kc; kk++) {
                u64 bv = __ldg(Bp); Bp += VLD / 2;
#pragma unroll
                for (int m = 0; m < 32; m++) acc[m] = ffma2(As2[kk][m], bv, acc[m]);
            }
            u64* Pp = (u64*)&d_P2[0][0][0] + (size_t)(ks * 32) * (VLD / 2) + np;
#pragma unroll
            for (int m = 0; m < 32; m++) Pp[(size_t)m * (VLD / 2)] = acc[m];
        } else if (bid < 292) {
            int idx = bid - 260, l = idx & 1, ks = idx >> 1, k0 = ks * 32;
            __syncthreads();
            for (int i = tid; i < 1024; i += NT) {
                int kk = i & 31, m = i >> 5;
                As2[kk][m] = dup2(d_hB[l][m][k0 + kk]);
            }
            __syncthreads();
            const u64* Bp = (const u64*)&d_WqT[k0][0] + tid;
            u64 acc[32];
#pragma unroll
            for (int m = 0; m < 32; m++) acc[m] = 0ull;
#pragma unroll 4
            for (int kk = 0; kk < 32; kk++) {
                u64 bv = __ldg(Bp); Bp += 256;
#pragma unroll
                for (int m = 0; m < 32; m++) acc[m] = ffma2(As2[kk][m], bv, acc[m]);
            }
            u64* Pp = (u64*)&d_Pq[0][0][0] + (size_t)(ks * 64 + l * 32) * 256 + tid;
#pragma unroll
            for (int m = 0; m < 32; m++) Pp[(size_t)m * 256] = acc[m];
        } else if (bid == 292) {
            if (tid < 32) d_bestKey[tid] = 0ull;
        }
        gsync(gen, bid);
        // ===== F: proj combine+logits+argmax (128) || q combine+tanh (16) =====
        if (bid < 128) {
            int b = bid >> 2, q = bid & 3;
            const u64* P2u = (const u64*)&d_P2[0][0][0];
            const u64* pb2 = (const u64*)projb;
            float best = -FLT_MAX; int bidx = 0x7fffffff;
#pragma unroll
            for (int i = 0; i < 5; i++) {
                int vp = q * 1280 + i * 256 + tid;
                u64 s = 0ull;
#pragma unroll
                for (int ks = 0; ks < 13; ks++)
                    s = fadd2(s, P2u[(size_t)(ks * 32 + b) * 5120 + vp]);
                if (vp < 5000) {
                    s = fadd2(s, pb2[vp]);
                    ((u64*)&d_logits[0][0][0])[((size_t)(t + 1) * 32 + b) * 5000 + vp] = s;
                    float lo = lo2(s), hi = hi2(s);
                    if (lo > best) { best = lo; bidx = 2 * vp; }
                    if (hi > best) { best = hi; bidx = 2 * vp + 1; }
                }
            }
            red[tid] = best; ridx[tid] = bidx;
            __syncthreads();
            for (int off = 128; off; off >>= 1) {
                if (tid < off) {
                    float ov = red[tid + off]; int oi = ridx[tid + off];
                    if (ov > red[tid] || (ov == red[tid] && oi < ridx[tid])) {
                        red[tid] = ov; ridx[tid] = oi;
                    }
                }
                __syncthreads();
            }
            if (!tid) {
                unsigned u = __float_as_uint(red[0]);
                unsigned mk = u ^ (unsigned)(((int)u >> 31) | 0x80000000);
                u64 key = ((u64)mk << 32) | (u64)(0xFFFFFFFFu - (unsigned)ridx[0]);
                atomicMax(&d_bestKey[b], key);
            }
        } else if (bid < 144) {
            int gid = (bid - 128) * 256 + tid;
            const u64* Pq2 = (const u64*)&d_Pq[0][0][0];
            const u64* bq2 = (const u64*)bq;
#pragma unroll
            for (int rep = 0; rep < 4; rep++) {
                int p = rep * 4096 + gid;
                int r = p >> 8, pr = p & 255;
                u64 s = 0ull;
#pragma unroll
                for (int ks = 0; ks < 16; ks++)
                    s = fadd2(s, Pq2[(size_t)(ks * 64 + r) * 256 + pr]);
                s = fadd2(s, bq2[pr]);
                ((u64*)&d_q[0][0])[(size_t)r * 256 + pr] = pack2(tanhf(lo2(s)), tanhf(hi2(s)));
            }
        }
        gsync(gen, bid);

        if (t < TMAX - 2) {
            // ===== G: attention (64 blks) + best decode (first 32) =====
            if (bid < 64) {
                int r = bid, b = r & 31;
                if (r < 32 && tid == 0) {
                    unsigned low = (unsigned)(d_bestKey[r] & 0xFFFFFFFFull);
                    d_best[r] = (int)(0xFFFFFFFFu - low);
                }
                __syncthreads();
                const float* qr = &d_q[r][0];
                for (int i = tid; i < 512; i += NT) xs[i] = qr[i];
                __syncthreads();
                int warp = tid >> 5, lane = tid & 31;
                for (int s = warp; s < SPA; s += 8) {
                    const float* kp = &d_keys[b][s][0];
                    float a = 0.f;
                    for (int k = lane; k < HID; k += 32) a += xs[k] * kp[k];
                    for (int o = 16; o; o >>= 1) a += __shfl_xor_sync(0xffffffffu, a, o);
                    if (!lane) wts[s] = a * (1.f / 7.f);
                }
                __syncthreads();
                if (warp == 0) {
                    float v1 = (lane < SPA) ? wts[lane] : -FLT_MAX;
                    float v2 = (lane + 32 < SPA) ? wts[lane + 32] : -FLT_MAX;
                    float m = fmaxf(v1, v2);
                    for (int o = 16; o; o >>= 1) m = fmaxf(m, __shfl_xor_sync(0xffffffffu, m, o));
                    float e1 = (lane < SPA) ? expf(v1 - m) : 0.f;
                    float e2 = (lane + 32 < SPA) ? expf(v2 - m) : 0.f;
                    float ssum = e1 + e2;
                    for (int o = 16; o; o >>= 1) ssum += __shfl_xor_sync(0xffffffffu, ssum, o);
                    float inv = 1.f / ssum;
                    if (lane < SPA) wts[lane] = e1 * inv;
                    if (lane + 32 < SPA) wts[lane + 32] = e2 * inv;
                }
                __syncthreads();
                const u64* V2 = (const u64*)&d_vals[0][0][0];
                u64 a = 0ull;
#pragma unroll
                for (int s = 0; s < SPA; s++)
                    a = ffma2(dup2(wts[s]), __ldg(V2 + (size_t)(b * SPA + s) * 256 + tid), a);
                ((u64*)&d_attn[0][0])[(size_t)r * 256 + tid] = a;
            }
            gsync(gen, bid);
            // ===== H: hatt gemm (32ks x 2l = 64 blks, KC=32) =====
            if (bid < 64) {
                int l = bid & 1, ks = bid >> 1, k0 = ks * 32;
                __syncthreads();
                for (int i = tid; i < 1024; i += NT) {
                    int kk = i & 31, m = i >> 5, k = k0 + kk;
                    int r = l * 32 + m;
                    float v = (k < 512) ? d_attn[r][k] : hB0[r * HID + (k - 512)];
                    As2[kk][m] = dup2(v);
                }
                __syncthreads();
                const u64* Bp = (const u64*)&d_hattWT[k0][0] + tid;
                u64 acc[32];
#pragma unroll
                for (int m = 0; m < 32; m++) acc[m] = 0ull;
#pragma unroll 4
                for (int kk = 0; kk < 32; kk++) {
                    u64 bv = __ldg(Bp); Bp += 256;
#pragma unroll
                    for (int m = 0; m < 32; m++) acc[m] = ffma2(As2[kk][m], bv, acc[m]);
                }
                u64* Pp = (u64*)&d_Ph[0][0][0] + (size_t)(ks * 64 + l * 32) * 256 + tid;
#pragma unroll
                for (int m = 0; m < 32; m++) Pp[(size_t)m * 256] = acc[m];
            }
            gsync(gen, bid);
            // ===== I: hatt combine + tanh -> hA (64 blks) =====
            if (bid < 64) {
                int r = bid;
                const u64* Ph2 = (const u64*)&d_Ph[0][0][0];
                u64 s = 0ull;
#pragma unroll
                for (int ks = 0; ks < 32; ks++)
                    s = fadd2(s, Ph2[(size_t)(ks * 64 + r) * 256 + tid]);
                s = fadd2(s, ((const u64*)hattb)[tid]);
                ((u64*)&d_hA[0][0][0])[(size_t)r * 256 + tid] = pack2(tanhf(lo2(s)), tanhf(hi2(s)));
            }
            gsync(gen, bid);
        }
    }
}

// ---------------- final [T][B][V] -> [B][V][T] ----------------
__global__ void out_transpose(float* __restrict__ out) {
    int b = blockIdx.x;
    int v0 = blockIdx.y * 128;
    __shared__ float tl[TMAX][129];
    int tid = threadIdx.x;
    for (int i = tid; i < TMAX * 128; i += 256) {
        int t = i >> 7, vi = i & 127;
        int v = v0 + vi;
        tl[t][vi] = (v < VOC) ? d_logits[t][b][v] : 0.f;
    }
    __syncthreads();
    for (int i = tid; i < 128 * TMAX; i += 256) {
        int vi = i / TMAX, t = i % TMAX;
        int v = v0 + vi;
        if (v < VOC) out[((size_t)b * VOC + v) * TMAX + t] = tl[t][vi];
    }
}

// ---------------- host ----------------
extern "C" void kernel_launch(void* const* d_in, const int* in_sizes, int n_in,
                              void* d_out, int out_size) {
    const float* img    = (const float*)d_in[0];
    const float* pooled = (const float*)d_in[1];
    const float* embed  = (const float*)d_in[2];
    const float* Wq     = (const float*)d_in[3];
    const float* bq     = (const float*)d_in[4];
    const float* Wk     = (const float*)d_in[5];
    const float* bk     = (const float*)d_in[6];
    const float* Wv     = (const float*)d_in[7];
    const float* bv     = (const float*)d_in[8];
    const float* Wih    = (const float*)d_in[9];
    const float* Whh    = (const float*)d_in[10];
    const float* bih    = (const float*)d_in[11];
    const float* bhh    = (const float*)d_in[12];
    const float* projW  = (const float*)d_in[13];
    const float* projb  = (const float*)d_in[14];
    const float* hattW  = (const float*)d_in[15];
    const float* hattb  = (const float*)d_in[16];
    const int*   sosp   = (const int*)d_in[17];
    float* out = (float*)d_out;

    dim3 tb(32, 8);
    transA<<<dim3(16, 64, 4), tb>>>(Wih, Whh);                               // 0
    transB<<<dim3(32, 313, 3), tb>>>(Wq, hattW, projW);                      // 1
    kvinit_kernel<<<dim3(32, 8), 256>>>(img, Wk, bk, Wv, bv, pooled, sosp);  // 2
    decode_loop<<<NB, NT>>>(embed, bih, bhh, projb, bq, hattb);              // 3 (abs idx 5)
    logits0_kernel<<<1250, 256>>>(embed, sosp, projW, projb);                // 4
    out_transpose<<<dim3(32, 79), 256>>>(out);                               // 5
    (void)in_sizes; (void)n_in; (void)out_size;
}

// round 10
// speedup vs baseline: 1.1754x; 1.1754x over previous
#include <cuda_runtime.h>
#include <math.h>
#include <stdint.h>
#include <float.h>

#define LNUM 2
#define HID 512
#define TMAX 20
#define VOC 10000
#define BAT 32
#define SPA 49
#define G4 2048
#define KXH 1024
#define VLD 10240
#define NB 256
#define NT 256

typedef unsigned long long u64;

__device__ __forceinline__ u64 ffma2(u64 a, u64 b, u64 c) {
    u64 d; asm("fma.rn.f32x2 %0, %1, %2, %3;" : "=l"(d) : "l"(a), "l"(b), "l"(c)); return d;
}
__device__ __forceinline__ u64 fadd2(u64 a, u64 b) {
    u64 d; asm("add.rn.f32x2 %0, %1, %2;" : "=l"(d) : "l"(a), "l"(b)); return d;
}
__device__ __forceinline__ u64 dup2(float x) {
    u64 d; unsigned u = __float_as_uint(x);
    asm("mov.b64 %0, {%1, %2};" : "=l"(d) : "r"(u), "r"(u)); return d;
}
__device__ __forceinline__ u64 pack2(float x, float y) {
    u64 d; unsigned a = __float_as_uint(x), b = __float_as_uint(y);
    asm("mov.b64 %0, {%1, %2};" : "=l"(d) : "r"(a), "r"(b)); return d;
}
__device__ __forceinline__ float lo2(u64 v) { return __uint_as_float((unsigned)v); }
__device__ __forceinline__ float hi2(u64 v) { return __uint_as_float((unsigned)(v >> 32)); }
__device__ __forceinline__ float sigm(float x) { return 1.f / (1.f + expf(-x)); }

// ---------------- static device scratch ----------------
__device__ float d_WcT[LNUM][KXH][G4];        // [l][k][n]
__device__ float d_WqT[HID][HID];             // [k][d]
__device__ float d_hattWT[KXH][HID];          // [k][j]
__device__ float d_projWT[HID][VLD];          // [k][v] padded (pad stays 0)
__device__ float d_keys[BAT][SPA][HID];
__device__ float d_vals[BAT][SPA][HID];
__device__ float d_hA[LNUM][BAT][HID];
__device__ float d_hB[LNUM][BAT][HID];
__device__ float d_cst[LNUM][BAT][HID];
__device__ float d_attn[LNUM*BAT][HID];
__device__ float d_P1[32][BAT][G4];           // LSTM partials (ksplit 32)
__device__ float d_P2[16][BAT][VLD];          // proj partials (ksplit 11)
__device__ float d_Pq[16][LNUM*BAT][HID];     // q partials (ksplit 16)
__device__ float d_Ph[32][LNUM*BAT][HID];     // hatt partials (ksplit 32)
__device__ float d_logits[TMAX][BAT][VOC];
__device__ u64   d_bestKey[BAT];              // packed (mapped-float | ~idx); atomicMax
__device__ unsigned g_count;
__device__ unsigned g_gen;

// ---------------- multi-job transposes ----------------
__global__ void transA(const float* __restrict__ Wih, const float* __restrict__ Whh) {
    __shared__ float tile[32][33];
    int z = blockIdx.z;
    const float* in = (z & 1) ? Whh : Wih;
    if (z >= 2) in += 2048 * 512;
    float* out = &d_WcT[0][0][0] + (size_t)(z >= 2 ? KXH : 0) * G4 + (size_t)(z & 1 ? 512 : 0) * G4;
    int c0 = blockIdx.x * 32, r0 = blockIdx.y * 32;
    int x = threadIdx.x;
    for (int y = threadIdx.y; y < 32; y += 8) {
        int r = r0 + y, c = c0 + x;
        tile[y][x] = (r < 2048 && c < 512) ? in[(size_t)r * 512 + c] : 0.f;
    }
    __syncthreads();
    for (int y = threadIdx.y; y < 32; y += 8) {
        int c = c0 + y, r = r0 + x;
        if (c < 512 && r < 2048) out[(size_t)c * G4 + r] = tile[x][y];
    }
}

__global__ void transB(const float* __restrict__ Wq, const float* __restrict__ hattW,
                       const float* __restrict__ projW) {
    __shared__ float tile[32][33];
    int z = blockIdx.z;
    const float* in; float* out; int R, C, oLd;
    if (z == 0)      { in = Wq;    out = &d_WqT[0][0];    R = 512;  C = 512;  oLd = 512; }
    else if (z == 1) { in = hattW; out = &d_hattWT[0][0]; R = 512;  C = 1024; oLd = 512; }
    else             { in = projW; out = &d_projWT[0][0]; R = VOC;  C = 512;  oLd = VLD; }
    int c0 = blockIdx.x * 32, r0 = blockIdx.y * 32;
    if (c0 >= C || r0 >= R) return;
    int x = threadIdx.x;
    for (int y = threadIdx.y; y < 32; y += 8) {
        int r = r0 + y, c = c0 + x;
        tile[y][x] = (r < R && c < C) ? in[(size_t)r * C + c] : 0.f;
    }
    __syncthreads();
    for (int y = threadIdx.y; y < 32; y += 8) {
        int c = c0 + y, r = r0 + x;
        if (c < C && r < R) out[(size_t)c * oLd + r] = tile[x][y];
    }
}

// ---------------- keys / values precompute + state init ----------------
__global__ void kvinit_kernel(const float* __restrict__ chan, const float* __restrict__ Wk,
                              const float* __restrict__ bk, const float* __restrict__ Wv,
                              const float* __restrict__ bv, const float* __restrict__ pooled,
                              const int* __restrict__ sosp) {
    int b = blockIdx.x;
    int d0 = blockIdx.y * 64;
    __shared__ float ct[64][SPA];
    __shared__ float wk[SPA][SPA], wv[SPA][SPA];
    __shared__ float bks[SPA], bvs[SPA];
    int tid = threadIdx.x;
    if (blockIdx.y == 0) {
        for (int j = tid; j < HID; j += 256) {
            float pv = pooled[b * HID + j];
            d_hA[0][b][j] = pv; d_hA[1][b][j] = pv;
            d_cst[0][b][j] = pv; d_cst[1][b][j] = pv;
        }
        if (tid == 0) {
            // encode <SOS> so step-0 decode (0xFFFFFFFF - low32) yields sos
            d_bestKey[b] = (u64)(0xFFFFFFFFu - (unsigned)sosp[0]);
            if (b == 0) { g_count = 0; g_gen = 0; }
        }
    }
    for (int i = tid; i < 64 * SPA; i += 256) {
        int d = i / SPA, s = i % SPA;
        ct[d][s] = chan[((size_t)b * HID + d0 + d) * SPA + s];
    }
    for (int i = tid; i < SPA * SPA; i += 256) {
        wk[i / SPA][i % SPA] = Wk[i];
        wv[i / SPA][i % SPA] = Wv[i];
    }
    if (tid < SPA) { bks[tid] = bk[tid]; bvs[tid] = bv[tid]; }
    __syncthreads();
    for (int i = tid; i < SPA * 64; i += 256) {
        int d = i & 63, s = i >> 6;
        float ak = bks[s], av = bvs[s];
#pragma unroll
        for (int sp = 0; sp < SPA; sp++) {
            float cv = ct[d][sp];
            ak += cv * wk[s][sp];
            av += cv * wv[s][sp];
        }
        d_keys[b][s][d0 + d] = tanhf(ak);
        d_vals[b][s][d0 + d] = tanhf(av);
    }
}

// ---------------- res[:,:,0] (identical across batch) ----------------
__global__ void logits0_kernel(const float* __restrict__ embed, const int* __restrict__ sosp,
                               const float* __restrict__ projW, const float* __restrict__ projb) {
    int warp = threadIdx.x >> 5, lane = threadIdx.x & 31;
    int v = blockIdx.x * 8 + warp;
    if (v >= VOC) return;
    int sos = sosp[0];
    const float* e = embed + (size_t)sos * HID;
    const float* w = projW + (size_t)v * HID;
    float acc = 0.f;
    for (int k = lane; k < HID; k += 32) acc += e[k] * w[k];
    for (int o = 16; o; o >>= 1) acc += __shfl_xor_sync(0xffffffffu, acc, o);
    float s = acc + projb[v];
    d_logits[0][lane][v] = s;   // lane == b
}

// ---------------- flat grid barrier (R6-proven) ----------------
__device__ __forceinline__ void gsync(unsigned& gen) {
    __syncthreads();
    if (threadIdx.x == 0) {
        gen++;
        __threadfence();
        if (atomicAdd(&g_count, 1) == NB - 1) {
            g_count = 0;
            __threadfence();
            *(volatile unsigned*)&g_gen = gen;
        } else {
            while (*(volatile unsigned*)&g_gen < gen) {}
        }
        __threadfence();
    }
    __syncthreads();
}

__global__ void __launch_bounds__(NT, 2) decode_loop(
    const float* __restrict__ embed, const float* __restrict__ bih,
    const float* __restrict__ bhh, const float* __restrict__ projb,
    const float* __restrict__ bq, const float* __restrict__ hattb)
{
    unsigned gen = *(volatile unsigned*)&g_gen;
    int bid = blockIdx.x, tid = threadIdx.x;
    __shared__ __align__(16) char shraw[64 * 33 * 8];    // 16.9KB union
    __shared__ int sbest[32];
    float (*As)[33]  = (float(*)[33])shraw;              // scalar LSTM stage
    u64   (*As2)[33] = (u64(*)[33])shraw;                // f32x2 stage
    float* xs  = (float*)shraw;                           // attn q (512 floats)
    float* wts = (float*)(shraw + 2048);
    float* red = (float*)shraw;
    int*   ridx = (int*)(shraw + 1024);

    const float* hA0 = &d_hA[0][0][0];
    const float* hA1 = &d_hA[1][0][0];
    const float* hB0 = &d_hB[0][0][0];
    const float* hB1 = &d_hB[1][0][0];

    for (int t = 0; t < TMAX - 1; t++) {
        // ===== A / C: LSTM gemm scalar (32ks x 8nt = 256 blocks, KC=32) =====
        for (int l = 0; l < 2; l++) {
            {
                int ks = bid >> 3, nt = bid & 7, k0 = ks * 32;
                if (l == 0) {
                    if (tid < 32) {
                        unsigned low = (unsigned)(d_bestKey[tid] & 0xFFFFFFFFull);
                        sbest[tid] = (int)(0xFFFFFFFFu - low);
                    }
                }
                __syncthreads();
                for (int i = tid; i < 1024; i += NT) {
                    int kk = i & 31, m = i >> 5, k = k0 + kk;
                    float v;
                    if (l == 0) v = (k < 512) ? embed[(size_t)sbest[m] * HID + k] : hA0[m * HID + (k - 512)];
                    else        v = (k < 512) ? hB0[m * HID + k] : hA1[m * HID + (k - 512)];
                    As[kk][m] = v;
                }
                __syncthreads();
                int n = nt * 256 + tid;
                const float* Bp = &d_WcT[l][k0][0] + n;
                float acc[32];
#pragma unroll
                for (int m = 0; m < 32; m++) acc[m] = 0.f;
#pragma unroll 4
                for (int kk = 0; kk < 32; kk++) {
                    float bv = __ldg(Bp); Bp += G4;
#pragma unroll
                    for (int m = 0; m < 32; m++) acc[m] += As[kk][m] * bv;
                }
                float* Pp = &d_P1[0][0][0] + (size_t)(ks * 32) * G4 + n;
#pragma unroll
                for (int m = 0; m < 32; m++) Pp[(size_t)m * G4] = acc[m];
            }
            gsync(gen);
            // ===== B / D: activation spread over ALL 256 blocks (4 thr/output) =====
            {
                int gid = bid * NT + tid;            // 65536
                int outp = gid >> 2, qtr = gid & 3;  // outp < 16384
                int b = outp >> 9, j = outp & 511;
                float s0 = 0.f, s1 = 0.f, s2 = 0.f, s3 = 0.f;
                const float* P = &d_P1[0][0][0];
#pragma unroll
                for (int ks = qtr * 8; ks < qtr * 8 + 8; ks++) {
                    size_t base = (size_t)(ks * 32 + b) * G4 + j;
                    s0 += P[base];
                    s1 += P[base + 512];
                    s2 += P[base + 1024];
                    s3 += P[base + 1536];
                }
                s0 += __shfl_xor_sync(0xffffffffu, s0, 1);
                s0 += __shfl_xor_sync(0xffffffffu, s0, 2);
                s1 += __shfl_xor_sync(0xffffffffu, s1, 1);
                s1 += __shfl_xor_sync(0xffffffffu, s1, 2);
                s2 += __shfl_xor_sync(0xffffffffu, s2, 1);
                s2 += __shfl_xor_sync(0xffffffffu, s2, 2);
                s3 += __shfl_xor_sync(0xffffffffu, s3, 1);
                s3 += __shfl_xor_sync(0xffffffffu, s3, 2);
                if (qtr == 0) {
                    s0 += bih[l * G4 + j]        + bhh[l * G4 + j];
                    s1 += bih[l * G4 + 512 + j]  + bhh[l * G4 + 512 + j];
                    s2 += bih[l * G4 + 1024 + j] + bhh[l * G4 + 1024 + j];
                    s3 += bih[l * G4 + 1536 + j] + bhh[l * G4 + 1536 + j];
                    float i_ = sigm(s0), f_ = sigm(s1), gg = tanhf(s2), o_ = sigm(s3);
                    float c2 = f_ * d_cst[l][b][j] + i_ * gg;
                    float h2 = o_ * tanhf(c2);
                    d_cst[l][b][j] = c2;
                    d_hB[l][b][j] = h2;
                }
            }
            gsync(gen);
        }
        // ===== E: proj gemm (11ks x 20nt = 220) || q gemm (16ks x 2l = 32) || reset =====
        if (bid < 220) {
            int nt = bid % 20, ks = bid / 20;
            int k0 = (ks * 512) / 11, k1 = ((ks + 1) * 512) / 11;
            int kc = k1 - k0;
            __syncthreads();
            for (int i = tid; i < 32 * kc; i += NT) {
                int kk = i % kc, m = i / kc;
                As2[kk][m] = dup2(hB1[m * HID + k0 + kk]);
            }
            __syncthreads();
            int np = nt * 256 + tid;
            const u64* Bp = (const u64*)&d_projWT[k0][0] + np;
            u64 acc[32];
#pragma unroll
            for (int m = 0; m < 32; m++) acc[m] = 0ull;
#pragma unroll 4
            for (int kk = 0; kk < kc; kk++) {
                u64 bv = __ldg(Bp); Bp += VLD / 2;
#pragma unroll
                for (int m = 0; m < 32; m++) acc[m] = ffma2(As2[kk][m], bv, acc[m]);
            }
            u64* Pp = (u64*)&d_P2[0][0][0] + (size_t)(ks * 32) * (VLD / 2) + np;
#pragma unroll
            for (int m = 0; m < 32; m++) Pp[(size_t)m * (VLD / 2)] = acc[m];
        } else if (bid < 252) {
            int idx = bid - 220, l = idx & 1, ks = idx >> 1, k0 = ks * 32;
            __syncthreads();
            for (int i = tid; i < 1024; i += NT) {
                int kk = i & 31, m = i >> 5;
                As2[kk][m] = dup2(d_hB[l][m][k0 + kk]);
            }
            __syncthreads();
            const u64* Bp = (const u64*)&d_WqT[k0][0] + tid;
            u64 acc[32];
#pragma unroll
            for (int m = 0; m < 32; m++) acc[m] = 0ull;
#pragma unroll 4
            for (int kk = 0; kk < 32; kk++) {
                u64 bv = __ldg(Bp); Bp += 256;
#pragma unroll
                for (int m = 0; m < 32; m++) acc[m] = ffma2(As2[kk][m], bv, acc[m]);
            }
            u64* Pp = (u64*)&d_Pq[0][0][0] + (size_t)(ks * 64 + l * 32) * 256 + tid;
#pragma unroll
            for (int m = 0; m < 32; m++) Pp[(size_t)m * 256] = acc[m];
        } else if (bid == 252) {
            if (tid < 32) d_bestKey[tid] = 0ull;    // reset for this step's atomicMax
        }
        gsync(gen);
        // ===== F || G: proj combine+logits+argmax (128)  ||  q-combine+attention (64) =====
        if (bid < 128) {
            int b = bid >> 2, q = bid & 3;
            const u64* P2u = (const u64*)&d_P2[0][0][0];
            const u64* pb2 = (const u64*)projb;
            float best = -FLT_MAX; int bidx = 0x7fffffff;
#pragma unroll
            for (int i = 0; i < 5; i++) {
                int vp = q * 1280 + i * 256 + tid;
                u64 s = 0ull;
#pragma unroll
                for (int ks = 0; ks < 11; ks++)
                    s = fadd2(s, P2u[(size_t)(ks * 32 + b) * 5120 + vp]);
                if (vp < 5000) {
                    s = fadd2(s, pb2[vp]);
                    ((u64*)&d_logits[0][0][0])[((size_t)(t + 1) * 32 + b) * 5000 + vp] = s;
                    float lo = lo2(s), hi = hi2(s);
                    if (lo > best) { best = lo; bidx = 2 * vp; }
                    if (hi > best) { best = hi; bidx = 2 * vp + 1; }
                }
            }
            red[tid] = best; ridx[tid] = bidx;
            __syncthreads();
            for (int off = 128; off; off >>= 1) {
                if (tid < off) {
                    float ov = red[tid + off]; int oi = ridx[tid + off];
                    if (ov > red[tid] || (ov == red[tid] && oi < ridx[tid])) {
                        red[tid] = ov; ridx[tid] = oi;
                    }
                }
                __syncthreads();
            }
            if (!tid) {
                unsigned u = __float_as_uint(red[0]);
                unsigned mk = u ^ (unsigned)(((int)u >> 31) | 0x80000000);
                u64 key = ((u64)mk << 32) | (u64)(0xFFFFFFFFu - (unsigned)ridx[0]);
                atomicMax(&d_bestKey[b], key);
            }
        } else if (bid < 192 && t < TMAX - 2) {
            int r = bid - 128, b = r & 31;
            // inline q-combine: 16 ksplit partial sums -> tanh -> smem
            {
                const u64* Pq2 = (const u64*)&d_Pq[0][0][0];
                u64 s = 0ull;
#pragma unroll
                for (int ks = 0; ks < 16; ks++)
                    s = fadd2(s, Pq2[(size_t)(ks * 64 + r) * 256 + tid]);
                s = fadd2(s, ((const u64*)bq)[tid]);
                xs[2 * tid]     = tanhf(lo2(s));
                xs[2 * tid + 1] = tanhf(hi2(s));
            }
            __syncthreads();
            int warp = tid >> 5, lane = tid & 31;
            for (int s = warp; s < SPA; s += 8) {
                const float* kp = &d_keys[b][s][0];
                float a = 0.f;
                for (int k = lane; k < HID; k += 32) a += xs[k] * kp[k];
                for (int o = 16; o; o >>= 1) a += __shfl_xor_sync(0xffffffffu, a, o);
                if (!lane) wts[s] = a * (1.f / 7.f);
            }
            __syncthreads();
            if (warp == 0) {
                float v1 = (lane < SPA) ? wts[lane] : -FLT_MAX;
                float v2 = (lane + 32 < SPA) ? wts[lane + 32] : -FLT_MAX;
                float m = fmaxf(v1, v2);
                for (int o = 16; o; o >>= 1) m = fmaxf(m, __shfl_xor_sync(0xffffffffu, m, o));
                float e1 = (lane < SPA) ? expf(v1 - m) : 0.f;
                float e2 = (lane + 32 < SPA) ? expf(v2 - m) : 0.f;
                float ssum = e1 + e2;
                for (int o = 16; o; o >>= 1) ssum += __shfl_xor_sync(0xffffffffu, ssum, o);
                float inv = 1.f / ssum;
                if (lane < SPA) wts[lane] = e1 * inv;
                if (lane + 32 < SPA) wts[lane + 32] = e2 * inv;
            }
            __syncthreads();
            const u64* V2 = (const u64*)&d_vals[0][0][0];
            u64 a = 0ull;
#pragma unroll
            for (int s = 0; s < SPA; s++)
                a = ffma2(dup2(wts[s]), __ldg(V2 + (size_t)(b * SPA + s) * 256 + tid), a);
            ((u64*)&d_attn[0][0])[(size_t)r * 256 + tid] = a;
        }
        gsync(gen);

        if (t < TMAX - 2) {
            // ===== H: hatt gemm (32ks x 2l = 64 blks, KC=32, f32x2) =====
            if (bid < 64) {
                int l = bid & 1, ks = bid >> 1, k0 = ks * 32;
                __syncthreads();
                for (int i = tid; i < 1024; i += NT) {
                    int kk = i & 31, m = i >> 5, k = k0 + kk;
                    int r = l * 32 + m;
                    float v = (k < 512) ? d_attn[r][k] : hB0[r * HID + (k - 512)];
                    As2[kk][m] = dup2(v);
                }
                __syncthreads();
                const u64* Bp = (const u64*)&d_hattWT[k0][0] + tid;
                u64 acc[32];
#pragma unroll
                for (int m = 0; m < 32; m++) acc[m] = 0ull;
#pragma unroll 4
                for (int kk = 0; kk < 32; kk++) {
                    u64 bv = __ldg(Bp); Bp += 256;
#pragma unroll
                    for (int m = 0; m < 32; m++) acc[m] = ffma2(As2[kk][m], bv, acc[m]);
                }
                u64* Pp = (u64*)&d_Ph[0][0][0] + (size_t)(ks * 64 + l * 32) * 256 + tid;
#pragma unroll
                for (int m = 0; m < 32; m++) Pp[(size_t)m * 256] = acc[m];
            }
            gsync(gen);
            // ===== I: hatt combine + tanh -> hA, spread 128 blocks (2 thr/output) =====
            if (bid < 128) {
                int gid = bid * NT + tid;            // 32768
                int outp = gid >> 1, half = gid & 1; // outp < 16384
                int r = outp >> 8, pr = outp & 255;
                const u64* Ph2 = (const u64*)&d_Ph[0][0][0];
                u64 s = 0ull;
#pragma unroll
                for (int ks = half * 16; ks < half * 16 + 16; ks++)
                    s = fadd2(s, Ph2[(size_t)(ks * 64 + r) * 256 + pr]);
                float slo = lo2(s), shi = hi2(s);
                slo += __shfl_xor_sync(0xffffffffu, slo, 1);
                shi += __shfl_xor_sync(0xffffffffu, shi, 1);
                if (!half) {
                    u64 bb = ((const u64*)hattb)[pr];
                    ((u64*)&d_hA[0][0][0])[(size_t)r * 256 + pr] =
                        pack2(tanhf(slo + lo2(bb)), tanhf(shi + hi2(bb)));
                }
            }
            gsync(gen);
        }
    }
}

// ---------------- final [T][B][V] -> [B][V][T] ----------------
__global__ void out_transpose(float* __restrict__ out) {
    int b = blockIdx.x;
    int v0 = blockIdx.y * 128;
    __shared__ float tl[TMAX][129];
    int tid = threadIdx.x;
    for (int i = tid; i < TMAX * 128; i += 256) {
        int t = i >> 7, vi = i & 127;
        int v = v0 + vi;
        tl[t][vi] = (v < VOC) ? d_logits[t][b][v] : 0.f;
    }
    __syncthreads();
    for (int i = tid; i < 128 * TMAX; i += 256) {
        int vi = i / TMAX, t = i % TMAX;
        int v = v0 + vi;
        if (v < VOC) out[((size_t)b * VOC + v) * TMAX + t] = tl[t][vi];
    }
}

// ---------------- host ----------------
extern "C" void kernel_launch(void* const* d_in, const int* in_sizes, int n_in,
                              void* d_out, int out_size) {
    const float* img    = (const float*)d_in[0];
    const float* pooled = (const float*)d_in[1];
    const float* embed  = (const float*)d_in[2];
    const float* Wq     = (const float*)d_in[3];
    const float* bq     = (const float*)d_in[4];
    const float* Wk     = (const float*)d_in[5];
    const float* bk     = (const float*)d_in[6];
    const float* Wv     = (const float*)d_in[7];
    const float* bv     = (const float*)d_in[8];
    const float* Wih    = (const float*)d_in[9];
    const float* Whh    = (const float*)d_in[10];
    const float* bih    = (const float*)d_in[11];
    const float* bhh    = (const float*)d_in[12];
    const float* projW  = (const float*)d_in[13];
    const float* projb  = (const float*)d_in[14];
    const float* hattW  = (const float*)d_in[15];
    const float* hattb  = (const float*)d_in[16];
    const int*   sosp   = (const int*)d_in[17];
    float* out = (float*)d_out;

    dim3 tb(32, 8);
    transA<<<dim3(16, 64, 4), tb>>>(Wih, Whh);                               // 0
    transB<<<dim3(32, 313, 3), tb>>>(Wq, hattW, projW);                      // 1
    kvinit_kernel<<<dim3(32, 8), 256>>>(img, Wk, bk, Wv, bv, pooled, sosp);  // 2
    decode_loop<<<NB, NT>>>(embed, bih, bhh, projb, bq, hattb);              // 3
    logits0_kernel<<<1250, 256>>>(embed, sosp, projW, projb);                // 4
    out_transpose<<<dim3(32, 79), 256>>>(out);                               // 5
    (void)in_sizes; (void)n_in; (void)out_size;
}